// round 11
// baseline (speedup 1.0000x reference)
#include <cuda_runtime.h>
#include <math.h>
#include <stdint.h>

// Problem constants
#define ANCH        8
#define INDIM       1024
#define ROWS_TOTAL  32768              // 64 * 512
#define ROWS_PER_CTA 256               // 2 rows per thread
#define NTHREADS    128
#define ROWGROUPS   (ROWS_TOTAL / ROWS_PER_CTA)   // 128
#define SPLITS      4
#define DSPLIT      (INDIM / SPLITS)   // 256
#define CHUNK       16
#define NCH         (DSPLIT / CHUNK)   // 16

// Scratch: per-split partial logits, per-rowgroup loss partials, completion counters.
__device__ float g_partial[SPLITS][ROWS_TOTAL][16];   // 8 MB
__device__ float g_lsum[ROWGROUPS];
__device__ float g_lcnt[ROWGROUPS];
__device__ int   g_done[ROWGROUPS];    // zero-init; reset in-kernel each launch
__device__ int   g_done2;              // zero-init; reset in-kernel each launch

// Packed fp32x2 FMA (Blackwell FFMA2; PTX-only)
#define FMA2(d, a, b, c) \
    asm("fma.rn.f32x2 %0, %1, %2, %3;" : "=l"(d) : "l"(a), "l"(b), "l"(c))
#define PACK2(o, lo, hi) \
    asm("mov.b64 %0, {%1, %2};" : "=l"(o) : "f"(lo), "f"(hi))
#define UNPACK2(lo, hi, in) \
    asm("mov.b64 {%0, %1}, %2;" : "=f"(lo), "=f"(hi) : "l"(in))

// X-tile swizzle: row r, float4-chunk c (0..3) lives at float offset 16r + (((r>>1)+c)&3)*4.
// Conflict-free for both the store phase (lanes 0-7 = rows 8w..8w+1, c 0..3) and the
// compute phase (lane l reads row l / row l+128) per 8-lane LDS/STS.128 phase.
__device__ __forceinline__ int xsw(int r, int c) {
    return r * 16 + ((((r >> 1) + c) & 3) << 2);
}

extern __shared__ float smem_dyn[];
// smem: W-slice [0, 4096) ; X buf0 [4096, 8192) ; X buf1 [8192, 12288)  => 49152 bytes

__global__ __launch_bounds__(NTHREADS, 4) void rpn_fused_kernel(
    const float* __restrict__ X,      // (32768, 1024)
    const float* __restrict__ W,      // (1024, 16)
    const float* __restrict__ bias,   // (16,)
    const int*   __restrict__ labels, // (32768, 8)
    float* __restrict__ out,
    int write_full)
{
    float* Ws  = smem_dyn;                     // 256 x 16
    float* Xs0 = smem_dyn + DSPLIT * 16;       // 256 rows x 16 (swizzled)
    float* Xs1 = Xs0 + ROWS_PER_CTA * CHUNK;
    const int tid = threadIdx.x;
    const int rg  = blockIdx.x;                // row group 0..127
    const int sp  = blockIdx.y;                // d split  0..3
    const int rowBase = rg * ROWS_PER_CTA;
    const int r0 = rowBase + tid;              // this thread's two rows
    const int r1 = rowBase + tid + 128;
    const int dBase = sp * DSPLIT;

    // Per-thread staging indices: i = tid + k*128 -> (row, float4-col) of the chunk tile
    const float* srcX = X + (size_t)rowBase * INDIM + dBase;

    // ---- Prologue ----
    // Stage W slice (4096 floats = 1024 float4)
    {
        const float4* Wg = (const float4*)(W + (size_t)dBase * 16);
        float4* Wd = (float4*)Ws;
        #pragma unroll
        for (int k = 0; k < 8; ++k) {
            const int i = tid + k * NTHREADS;
            Wd[i] = Wg[i];
        }
    }
    // Stage chunk 0 into buf0 (LDG -> STS)
    {
        #pragma unroll
        for (int k = 0; k < 8; ++k) {
            const int i = tid + k * NTHREADS;
            const int r = i >> 2, c = i & 3;
            float4 v = *(const float4*)(srcX + (size_t)r * INDIM + c * 4);
            *(float4*)(Xs0 + xsw(r, c)) = v;
        }
    }
    // Prefetch chunk 1 into registers
    float4 xreg[8];
    #pragma unroll
    for (int k = 0; k < 8; ++k) {
        const int i = tid + k * NTHREADS;
        const int r = i >> 2, c = i & 3;
        xreg[k] = *(const float4*)(srcX + (size_t)r * INDIM + CHUNK + c * 4);
    }
    __syncthreads();

    // Accumulators: 8 packed f32x2 per row = 16 outputs each
    unsigned long long accA[8], accB[8];
    #pragma unroll
    for (int p = 0; p < 8; ++p) { accA[p] = 0ull; accB[p] = 0ull; }

    #pragma unroll 1
    for (int ch = 0; ch < NCH; ++ch) {
        // Drain registers (chunk ch+1) into the alternate buffer.
        // Safe: the sync ending iteration ch-1 guarantees everyone finished
        // reading buf[(ch+1)&1] (= buf[(ch-1)&1]) before these STS.
        if (ch + 1 < NCH) {
            float* nbuf = ((ch + 1) & 1) ? Xs1 : Xs0;
            #pragma unroll
            for (int k = 0; k < 8; ++k) {
                const int i = tid + k * NTHREADS;
                const int r = i >> 2, c = i & 3;
                *(float4*)(nbuf + xsw(r, c)) = xreg[k];
            }
        }
        // Prefetch chunk ch+2 into registers (latency hidden by this chunk's compute)
        if (ch + 2 < NCH) {
            const float* src_base = srcX + (ch + 2) * CHUNK;
            #pragma unroll
            for (int k = 0; k < 8; ++k) {
                const int i = tid + k * NTHREADS;
                const int r = i >> 2, c = i & 3;
                xreg[k] = *(const float4*)(src_base + (size_t)r * INDIM + c * 4);
            }
        }

        const float* xb = (ch & 1) ? Xs1 : Xs0;
        const ulonglong2* wch = (const ulonglong2*)(Ws + ch * CHUNK * 16);

        #pragma unroll
        for (int c = 0; c < 4; ++c) {
            const float4 va = *(const float4*)(xb + xsw(tid, c));
            const float4 vb = *(const float4*)(xb + xsw(tid + 128, c));
            #pragma unroll
            for (int j = 0; j < 4; ++j) {
                const float aj = (j == 0) ? va.x : (j == 1) ? va.y : (j == 2) ? va.z : va.w;
                const float bj = (j == 0) ? vb.x : (j == 1) ? vb.y : (j == 2) ? vb.z : vb.w;
                unsigned long long xa, xbp;
                PACK2(xa, aj, aj);
                PACK2(xbp, bj, bj);
                const ulonglong2* wr = wch + (c * 4 + j) * 4;   // 16 floats = 4x LDS.128 broadcast
                const ulonglong2 w0 = wr[0], w1 = wr[1], w2 = wr[2], w3 = wr[3];
                FMA2(accA[0], xa,  w0.x, accA[0]);
                FMA2(accA[1], xa,  w0.y, accA[1]);
                FMA2(accA[2], xa,  w1.x, accA[2]);
                FMA2(accA[3], xa,  w1.y, accA[3]);
                FMA2(accA[4], xa,  w2.x, accA[4]);
                FMA2(accA[5], xa,  w2.y, accA[5]);
                FMA2(accA[6], xa,  w3.x, accA[6]);
                FMA2(accA[7], xa,  w3.y, accA[7]);
                FMA2(accB[0], xbp, w0.x, accB[0]);
                FMA2(accB[1], xbp, w0.y, accB[1]);
                FMA2(accB[2], xbp, w1.x, accB[2]);
                FMA2(accB[3], xbp, w1.y, accB[3]);
                FMA2(accB[4], xbp, w2.x, accB[4]);
                FMA2(accB[5], xbp, w2.y, accB[5]);
                FMA2(accB[6], xbp, w3.x, accB[6]);
                FMA2(accB[7], xbp, w3.y, accB[7]);
            }
        }
        __syncthreads();   // reads of buf[ch&1] done; next iter may STS into it
    }

    // ---- Store this split's partial logits (16 floats per row, both rows) ----
    {
        float pa[16], pb[16];
        #pragma unroll
        for (int p = 0; p < 8; ++p) {
            UNPACK2(pa[2 * p], pa[2 * p + 1], accA[p]);
            UNPACK2(pb[2 * p], pb[2 * p + 1], accB[p]);
        }
        float4* dA = (float4*)g_partial[sp][r0];
        float4* dB = (float4*)g_partial[sp][r1];
        #pragma unroll
        for (int q = 0; q < 4; ++q) {
            dA[q] = make_float4(pa[4 * q], pa[4 * q + 1], pa[4 * q + 2], pa[4 * q + 3]);
            dB[q] = make_float4(pb[4 * q], pb[4 * q + 1], pb[4 * q + 2], pb[4 * q + 3]);
        }
    }
    __threadfence();          // publish partials
    __syncthreads();

    // ---- Last CTA of this row group runs the fused epilogue ----
    __shared__ int s_flag;
    if (tid == 0) {
        int old = atomicAdd(&g_done[rg], 1);
        s_flag = (old == SPLITS - 1) ? 1 : 0;
        if (s_flag) g_done[rg] = 0;   // reset for next replay
    }
    __syncthreads();
    if (!s_flag) return;
    __threadfence();          // acquire: all splits' partials visible

    float lsum = 0.f, lcnt = 0.f;
    const int wid = tid >> 5, lid = tid & 31;

    #pragma unroll
    for (int rr = 0; rr < 2; ++rr) {
        const int row = (rr == 0) ? r0 : r1;
        // Gather all splits in fixed order (deterministic summation)
        float lg[16];
        #pragma unroll
        for (int k = 0; k < 16; ++k) lg[k] = __ldg(bias + k);
        #pragma unroll
        for (int s = 0; s < SPLITS; ++s) {
            const float4* pp = (const float4*)g_partial[s][row];
            const float4 a = pp[0], b2 = pp[1], c2 = pp[2], d2 = pp[3];
            lg[0]  += a.x;  lg[1]  += a.y;  lg[2]  += a.z;  lg[3]  += a.w;
            lg[4]  += b2.x; lg[5]  += b2.y; lg[6]  += b2.z; lg[7]  += b2.w;
            lg[8]  += c2.x; lg[9]  += c2.y; lg[10] += c2.z; lg[11] += c2.w;
            lg[12] += d2.x; lg[13] += d2.y; lg[14] += d2.z; lg[15] += d2.w;
        }

        const int* lab = labels + (size_t)row * ANCH;
        float pred[ANCH], msk[ANCH];
        #pragma unroll
        for (int a = 0; a < ANCH; ++a) {
            const float l0 = lg[2 * a], l1 = lg[2 * a + 1];
            const int lb = lab[a];
            const bool p1 = (l1 > l0);        // jnp.argmax: first max wins ties -> strict >
            const bool valid = (lb != -1);
            const float m = fmaxf(l0, l1);
            const float lse = m + logf(expf(l0 - m) + expf(l1 - m));
            const float chosen = (lb == 1) ? l1 : l0;
            if (valid) { lsum += lse - chosen; lcnt += 1.f; }
            pred[a] = p1 ? 1.f : 0.f;
            msk[a]  = (p1 && valid) ? 1.f : 0.f;
        }

        if (write_full) {
            float* outPred = out + 1 + (size_t)row * ANCH;
            float* outMask = out + 1 + (size_t)ROWS_TOTAL * ANCH + (size_t)row * ANCH;
            #pragma unroll
            for (int a = 0; a < ANCH; ++a) { outPred[a] = pred[a]; outMask[a] = msk[a]; }
        }
    }

    // ---- Deterministic block reduction of (nll sum, valid count) ----
    #pragma unroll
    for (int off = 16; off; off >>= 1) {
        lsum += __shfl_down_sync(0xffffffffu, lsum, off);
        lcnt += __shfl_down_sync(0xffffffffu, lcnt, off);
    }
    __shared__ float red[8];
    if (lid == 0) { red[wid * 2] = lsum; red[wid * 2 + 1] = lcnt; }
    __syncthreads();
    if (tid == 0) {
        g_lsum[rg] = red[0] + red[2] + red[4] + red[6];
        g_lcnt[rg] = red[1] + red[3] + red[5] + red[7];
    }
    __threadfence();
    __syncthreads();

    // ---- Last row group computes the final loss ----
    __shared__ int s_flag2;
    if (tid == 0) {
        int old = atomicAdd(&g_done2, 1);
        s_flag2 = (old == ROWGROUPS - 1) ? 1 : 0;
        if (s_flag2) g_done2 = 0;
    }
    __syncthreads();
    if (!s_flag2) return;
    __threadfence();

    float s = g_lsum[tid];      // 128 rowgroups, 128 threads
    float c = g_lcnt[tid];
    #pragma unroll
    for (int off = 16; off; off >>= 1) {
        s += __shfl_down_sync(0xffffffffu, s, off);
        c += __shfl_down_sync(0xffffffffu, c, off);
    }
    __shared__ float fs[8];
    if (lid == 0) { fs[wid * 2] = s; fs[wid * 2 + 1] = c; }
    __syncthreads();
    if (tid == 0) {
        const float S = fs[0] + fs[2] + fs[4] + fs[6];
        const float C = fs[1] + fs[3] + fs[5] + fs[7];
        out[0] = S / fmaxf(C, 1.f);
    }
}

extern "C" void kernel_launch(void* const* d_in, const int* in_sizes, int n_in,
                              void* d_out, int out_size)
{
    // Map inputs by element count (robust to ordering); sizes are all distinct.
    const float* X = nullptr;
    const float* W = nullptr;
    const float* b = nullptr;
    const int*   lab = nullptr;
    for (int i = 0; i < n_in; ++i) {
        switch (in_sizes[i]) {
            case ROWS_TOTAL * INDIM:  X   = (const float*)d_in[i]; break; // 33554432
            case INDIM * 16:          W   = (const float*)d_in[i]; break; // 16384
            case 16:                  b   = (const float*)d_in[i]; break; // 16
            case ROWS_TOTAL * ANCH:   lab = (const int*)  d_in[i]; break; // 262144
            default: break;
        }
    }
    if (!X   && n_in > 0) X   = (const float*)d_in[0];
    if (!W   && n_in > 1) W   = (const float*)d_in[1];
    if (!b   && n_in > 2) b   = (const float*)d_in[2];
    if (!lab && n_in > 3) lab = (const int*)  d_in[3];

    float* out = (float*)d_out;
    const int write_full = (out_size >= 1 + 2 * ROWS_TOTAL * ANCH) ? 1 : 0;

    const size_t smem_bytes = (size_t)(DSPLIT * 16 + 2 * ROWS_PER_CTA * CHUNK) * sizeof(float); // 49152
    cudaFuncSetAttribute(rpn_fused_kernel, cudaFuncAttributeMaxDynamicSharedMemorySize, (int)smem_bytes);

    dim3 grid(ROWGROUPS, SPLITS);
    rpn_fused_kernel<<<grid, NTHREADS, smem_bytes>>>(X, W, b, lab, out, write_full);
}